// round 1
// baseline (speedup 1.0000x reference)
#include <cuda_runtime.h>
#include <cuda_bf16.h>

// PCEN: m[0]=x[0]; m[t] = (1-s)*m[t-1] + s*x[t];  out = (x/(eps+m)^0.98 + 2)^0.5 - 2^0.5
// Exact parallel linear-recurrence scan: constant per-row decay a = 1-s makes the
// recurrence an exponentially weighted prefix sum -> 3-level scan
// (regs -> warp shuffle -> cross-warp smem), x kept in registers, 1 read + 1 write.

#define TT    8000
#define EPT   32          // elements per thread
#define NTH   256
#define ALPHA_C 0.98f
#define DELTA_C 2.0f
#define EPS_C   1e-6f
#define SQRT_DELTA 1.41421356237f

__global__ __launch_bounds__(NTH)
void pcen_kernel(const float* __restrict__ x,
                 const float* __restrict__ log_s,
                 float* __restrict__ out,
                 int F)
{
    const int row = blockIdx.x;
    const int f   = row % F;
    const float s = __expf(log_s[f]);
    const float a = 1.0f - s;

    const float* xr   = x   + (long long)row * TT;
    float*       orow = out + (long long)row * TT;

    const int t    = threadIdx.x;
    const int base = t * EPT;
    const bool active = (base < TT);      // 250 of 256 threads carry data

    // ---- load 32 contiguous elements into registers (8x LDG.128) ----
    float xv[EPT];
    if (active) {
        const float4* p = (const float4*)(xr + base);
        #pragma unroll
        for (int i = 0; i < EPT/4; i++) {
            float4 v = p[i];
            xv[4*i+0] = v.x; xv[4*i+1] = v.y; xv[4*i+2] = v.z; xv[4*i+3] = v.w;
        }
    } else {
        #pragma unroll
        for (int i = 0; i < EPT; i++) xv[i] = 0.0f;
    }

    // ---- pass 1: thread-local zero-init scan -> segment total Fv ----
    // w[0] = x[0] (init condition), w[t>=1] = s*x[t]
    float Fv = 0.0f;
    #pragma unroll
    for (int i = 0; i < EPT; i++) {
        float w = s * xv[i];
        if (t == 0 && i == 0) w = xv[0];
        Fv = fmaf(a, Fv, w);
    }
    if (!active) Fv = 0.0f;

    // D = a^EPT (decay across one thread segment)
    float D = a;
    #pragma unroll
    for (int k = 0; k < 5; k++) D = D * D;   // a^32

    const int lane = t & 31;
    const int wid  = t >> 5;

    // ---- level 2: Hillis-Steele warp scan with decay ----
    float val = Fv;       // inclusive zero-init scan value
    float pw  = D;        // D^(2^k) at step k
    float pl  = 1.0f;     // accumulates D^lane
    #pragma unroll
    for (int off = 1; off < 32; off <<= 1) {
        float up = __shfl_up_sync(0xFFFFFFFFu, val, off);
        if (lane & off) pl *= pw;
        if (lane >= off) val = fmaf(pw, up, val);
        pw = pw * pw;
    }
    const float Dw = pw;  // D^32 = a^1024 (decay across one warp's span)

    __shared__ float warpTot[NTH/32];
    if (lane == 31) warpTot[wid] = val;
    __syncthreads();

    // ---- level 3: exclusive cross-warp combine (<=7 iters, smem reads) ----
    float wex = 0.0f;
    for (int u = 0; u < wid; u++) wex = fmaf(Dw, wex, warpTot[u]);

    // exclusive-within-warp value
    float vex = __shfl_up_sync(0xFFFFFFFFu, val, 1);
    if (lane == 0) vex = 0.0f;

    // carry into this thread's segment: m[base-1] = D^lane * wex + vex
    const float carry = fmaf(pl, wex, vex);

    // ---- pass 2: replay recurrence with true carry, emit output ----
    if (active) {
        float m = carry;
        float ov[EPT];
        #pragma unroll
        for (int i = 0; i < EPT; i++) {
            float w = s * xv[i];
            if (t == 0 && i == 0) w = xv[0];
            m = fmaf(a, m, w);
            // (x * (eps+m)^-alpha + delta)^0.5 - delta^0.5
            float inv = __powf(EPS_C + m, -ALPHA_C);
            ov[i] = sqrtf(fmaf(xv[i], inv, DELTA_C)) - SQRT_DELTA;
        }
        float4* po = (float4*)(orow + base);
        #pragma unroll
        for (int i = 0; i < EPT/4; i++) {
            po[i] = make_float4(ov[4*i+0], ov[4*i+1], ov[4*i+2], ov[4*i+3]);
        }
    }
}

extern "C" void kernel_launch(void* const* d_in, const int* in_sizes, int n_in,
                              void* d_out, int out_size)
{
    // Robust to metadata ordering: x is the big input, log_s the small one.
    int xi = 0, si = 1;
    if (n_in >= 2 && in_sizes[0] < in_sizes[1]) { xi = 1; si = 0; }

    const float* x     = (const float*)d_in[xi];
    const float* log_s = (const float*)d_in[si];
    float*       out   = (float*)d_out;

    const int F    = in_sizes[si];           // 128
    const int rows = in_sizes[xi] / TT;      // B*F = 4096

    pcen_kernel<<<rows, NTH>>>(x, log_s, out, F);
}

// round 2
// speedup vs baseline: 1.1999x; 1.1999x over previous
#include <cuda_runtime.h>
#include <cuda_bf16.h>

// PCEN: m[0]=x[0]; m[t] = (1-s)*m[t-1] + s*x[t];  out = (x/(eps+m)^0.98 + 2)^0.5 - 2^0.5
// Exact parallel linear-recurrence scan (constant per-row decay a = 1-s).
// R2: EPT=8 / NTH=1024 to kill L1 wavefront inflation (lanes stride 32B ->
// 8 lines per LDG.128 warp-instr instead of 32). 3-level scan:
// regs(8) -> warp shuffle(32) -> warp0 scans 32 warp totals.

#define TT    8000
#define EPT   8            // elements per thread
#define NTH   1024
#define NWARP (NTH/32)
#define ALPHA_C 0.98f
#define DELTA_C 2.0f
#define EPS_C   1e-6f
#define SQRT_DELTA 1.41421356237f

__global__ __launch_bounds__(NTH)
void pcen_kernel(const float* __restrict__ x,
                 const float* __restrict__ log_s,
                 float* __restrict__ out,
                 int F)
{
    const int row = blockIdx.x;
    const int f   = row % F;
    const float s = __expf(log_s[f]);
    const float a = 1.0f - s;

    const float* xr   = x   + (long long)row * TT;
    float*       orow = out + (long long)row * TT;

    const int t    = threadIdx.x;
    const int base = t * EPT;
    const bool active = (base < TT);      // threads 0..999 carry data

    // ---- load 8 contiguous elements (2x LDG.128, lanes stride 32B) ----
    float xv[EPT];
    if (active) {
        const float4* p = (const float4*)(xr + base);
        float4 v0 = p[0];
        float4 v1 = p[1];
        xv[0]=v0.x; xv[1]=v0.y; xv[2]=v0.z; xv[3]=v0.w;
        xv[4]=v1.x; xv[5]=v1.y; xv[6]=v1.z; xv[7]=v1.w;
    } else {
        #pragma unroll
        for (int i = 0; i < EPT; i++) xv[i] = 0.0f;
    }

    // ---- pass 1: thread-local zero-init scan -> segment total Fv ----
    // w[0] = x[0] (init condition), w[t>=1] = s*x[t]
    float Fv = 0.0f;
    #pragma unroll
    for (int i = 0; i < EPT; i++) {
        float w = s * xv[i];
        if (t == 0 && i == 0) w = xv[0];
        Fv = fmaf(a, Fv, w);
    }
    if (!active) Fv = 0.0f;

    // D = a^EPT
    float D = a;
    #pragma unroll
    for (int k = 0; k < 3; k++) D = D * D;   // a^8

    const int lane = t & 31;
    const int wid  = t >> 5;

    // ---- level 2: Hillis-Steele warp scan with decay ----
    float val = Fv;       // inclusive zero-init scan value
    float pw  = D;        // D^(2^k)
    float pl  = 1.0f;     // D^lane
    #pragma unroll
    for (int off = 1; off < 32; off <<= 1) {
        float up = __shfl_up_sync(0xFFFFFFFFu, val, off);
        if (lane & off) pl *= pw;
        if (lane >= off) val = fmaf(pw, up, val);
        pw = pw * pw;
    }
    const float Dw = pw;  // D^32 = a^256 (decay across one warp's span)

    __shared__ float warpTot[NWARP];
    __shared__ float warpPre[NWARP];
    if (lane == 31) warpTot[wid] = val;
    __syncthreads();

    // ---- level 3: warp 0 scans the 32 warp totals with decay Dw ----
    if (wid == 0) {
        float v  = warpTot[lane];
        float w2 = Dw;
        #pragma unroll
        for (int off = 1; off < 32; off <<= 1) {
            float up = __shfl_up_sync(0xFFFFFFFFu, v, off);
            if (lane >= off) v = fmaf(w2, up, v);
            w2 = w2 * w2;
        }
        float ex = __shfl_up_sync(0xFFFFFFFFu, v, 1);   // exclusive prefix
        if (lane == 0) ex = 0.0f;
        warpPre[lane] = ex;
    }
    __syncthreads();

    // exclusive-within-warp value
    float vex = __shfl_up_sync(0xFFFFFFFFu, val, 1);
    if (lane == 0) vex = 0.0f;

    // carry into this thread's segment
    const float carry = fmaf(pl, warpPre[wid], vex);

    // ---- pass 2: replay recurrence with true carry, emit output ----
    if (active) {
        float m = carry;
        float ov[EPT];
        #pragma unroll
        for (int i = 0; i < EPT; i++) {
            float w = s * xv[i];
            if (t == 0 && i == 0) w = xv[0];
            m = fmaf(a, m, w);
            float inv = __powf(EPS_C + m, -ALPHA_C);
            ov[i] = sqrtf(fmaf(xv[i], inv, DELTA_C)) - SQRT_DELTA;
        }
        float4* po = (float4*)(orow + base);
        po[0] = make_float4(ov[0], ov[1], ov[2], ov[3]);
        po[1] = make_float4(ov[4], ov[5], ov[6], ov[7]);
    }
}

extern "C" void kernel_launch(void* const* d_in, const int* in_sizes, int n_in,
                              void* d_out, int out_size)
{
    // Robust to metadata ordering: x is the big input, log_s the small one.
    int xi = 0, si = 1;
    if (n_in >= 2 && in_sizes[0] < in_sizes[1]) { xi = 1; si = 0; }

    const float* x     = (const float*)d_in[xi];
    const float* log_s = (const float*)d_in[si];
    float*       out   = (float*)d_out;

    const int F    = in_sizes[si];           // 128
    const int rows = in_sizes[xi] / TT;      // B*F = 4096

    pcen_kernel<<<rows, NTH>>>(x, log_s, out, F);
}